// round 12
// baseline (speedup 1.0000x reference)
#include <cuda_runtime.h>
#include <cuda_bf16.h>
#include <cuda_fp16.h>
#include <cstdint>

#define NN 100000
#define NR 3
#define NE 300000

// ---- device scratch (no allocs allowed) ----
__device__ uint32_t g_z  [(size_t)NN * 192];  // transformed feats, half2-packed
__device__ uint32_t g_xh [(size_t)NN * 64];   // x split hi, packed bf16x2 [row][k2]
__device__ uint32_t g_xl [(size_t)NN * 64];
__device__ uint32_t g_hh [(size_t)NN * 64];   // relu(h1) split hi
__device__ uint32_t g_hl [(size_t)NN * 64];
__device__ uint32_t g_wh1[(size_t)NR * 128 * 64];  // W1^T split hi [rel][n][k2]
__device__ uint32_t g_wl1[(size_t)NR * 128 * 64];
__device__ uint32_t g_wh2[(size_t)NR * 64 * 64];   // W2^T split
__device__ uint32_t g_wl2[(size_t)NR * 64 * 64];
__device__ float    g_outd[NR * NN];
__device__ float    g_ind [NR * NN];
__device__ int      g_cnt_in [NR * NN];
__device__ int      g_cnt_out[NR * NN];
__device__ int      g_off[NR * NN];
__device__ int      g_cur[NR * NN];
__device__ int      g_csr[NR * NE];
__device__ int      g_cursor;

// ------------------------------------------------------------------
__global__ void k_hist(const int* __restrict__ E) {
    int i = blockIdx.x * blockDim.x + threadIdx.x;
    if (i >= NR * NE) return;
    int r = i / NE, e = i % NE;
    const int* Er = E + (size_t)r * 2 * NE;
    atomicAdd(&g_cnt_out[r * NN + Er[e]],      1);
    atomicAdd(&g_cnt_in [r * NN + Er[NE + e]], 1);
}

__global__ void k_finalize_reserve() {
    int i = blockIdx.x * blockDim.x + threadIdx.x;
    int lane = threadIdx.x & 31;
    int d = 0;
    if (i < NR * NN) {
        int cin = g_cnt_in[i];
        g_outd[i] = rsqrtf(fmaxf((float)g_cnt_out[i], 1.f));
        g_ind [i] = rsqrtf(fmaxf((float)cin, 1.f));
        d = cin;
    }
    int s = d;
    #pragma unroll
    for (int o = 1; o < 32; o <<= 1) {
        int t = __shfl_up_sync(0xffffffffu, s, o);
        if (lane >= o) s += t;
    }
    int total = __shfl_sync(0xffffffffu, s, 31);
    int base = 0;
    if (lane == 31) base = atomicAdd(&g_cursor, total);
    base = __shfl_sync(0xffffffffu, base, 31);
    if (i < NR * NN) {
        int start = base + s - d;
        g_off[i] = start;
        g_cur[i] = start;
    }
}

__global__ void k_fill(const int* __restrict__ E) {
    int i = blockIdx.x * blockDim.x + threadIdx.x;
    if (i >= NR * NE) return;
    int r = i / NE, e = i % NE;
    const int* Er = E + (size_t)r * 2 * NE;
    int src = Er[e];
    int dst = Er[NE + e];
    int slot = atomicAdd(&g_cur[r * NN + dst], 1);
    g_csr[slot] = src;
}

// ------------------------------------------------------------------
__device__ __forceinline__ uint32_t pack_bf16x2(float lo, float hi) {
    uint32_t r;
    asm("cvt.rn.bf16x2.f32 %0, %1, %2;" : "=r"(r) : "f"(hi), "f"(lo));
    return r;
}

__device__ __forceinline__ void bsplit(float f, float& h, float& l) {
    __nv_bfloat16 bh = __float2bfloat16_rn(f);
    h = __bfloat162float(bh);
    l = f - h;
}

__device__ __forceinline__ void mma_bf16(float* c, const uint32_t* a, const uint32_t* b) {
    asm volatile(
        "mma.sync.aligned.m16n8k16.row.col.f32.bf16.bf16.f32 "
        "{%0,%1,%2,%3}, {%4,%5,%6,%7}, {%8,%9}, {%0,%1,%2,%3};"
        : "+f"(c[0]), "+f"(c[1]), "+f"(c[2]), "+f"(c[3])
        : "r"(a[0]), "r"(a[1]), "r"(a[2]), "r"(a[3]),
          "r"(b[0]), "r"(b[1]));
}

__device__ __forceinline__ void ldsm_x4(uint32_t& r0, uint32_t& r1, uint32_t& r2, uint32_t& r3,
                                        uint32_t addr) {
    asm volatile("ldmatrix.sync.aligned.m8n8.x4.shared.b16 {%0,%1,%2,%3}, [%4];"
                 : "=r"(r0), "=r"(r1), "=r"(r2), "=r"(r3) : "r"(addr));
}

__device__ __forceinline__ uint32_t smem_u32(const void* p) {
    return (uint32_t)__cvta_generic_to_shared(p);
}

// split x -> packed hi/lo planes [row][k2]
__global__ void k_split_x(const float* __restrict__ X) {
    int i = blockIdx.x * blockDim.x + threadIdx.x;
    if (i >= NN * 32) return;
    int row = i >> 5, q = i & 31;
    float4 v = *(const float4*)&X[(size_t)row * 128 + q * 4];
    float h0, l0, h1, l1, h2, l2, h3, l3;
    bsplit(v.x, h0, l0); bsplit(v.y, h1, l1);
    bsplit(v.z, h2, l2); bsplit(v.w, h3, l3);
    uint2 ph = make_uint2(pack_bf16x2(h0, h1), pack_bf16x2(h2, h3));
    uint2 pl = make_uint2(pack_bf16x2(l0, l1), pack_bf16x2(l2, l3));
    *(uint2*)&g_xh[(size_t)row * 64 + q * 2] = ph;
    *(uint2*)&g_xl[(size_t)row * 64 + q * 2] = pl;
}

// split + transpose W -> [rel][n][k2] packed
template<int BN>
__global__ void k_split_wT(const float* __restrict__ W,
                           uint32_t* __restrict__ WH, uint32_t* __restrict__ WL) {
    int i = blockIdx.x * blockDim.x + threadIdx.x;
    if (i >= NR * BN * 64) return;
    int rel = i / (BN * 64);
    int rem = i % (BN * 64);
    int n  = rem / 64;
    int k2 = rem % 64;
    const float* Wr = W + (size_t)rel * 128 * BN;
    float f0 = Wr[(size_t)(2 * k2)     * BN + n];
    float f1 = Wr[(size_t)(2 * k2 + 1) * BN + n];
    float h0, l0, h1, l1;
    bsplit(f0, h0, l0);
    bsplit(f1, h1, l1);
    WH[i] = pack_bf16x2(h0, h1);
    WL[i] = pack_bf16x2(l0, l1);
}

// ------------------------------------------------------------------
// Z[row][rel*BN + c] = outd_rel[row] * sum_k in[row][k] * W[rel][k][c]
// Pre-split packed operands; ldmatrix feed; bf16 3-pass split mma.
// Block 128 x BN, 8 warps (4M x 2N). Smem tiles [rows][36] per 64-k chunk.
template<int BN, int WSTW>
__global__ __launch_bounds__(256, 2) void k_gemm_lm(
    const uint32_t* __restrict__ XH, const uint32_t* __restrict__ XL,
    const uint32_t* __restrict__ WTH, const uint32_t* __restrict__ WTL,
    const float* __restrict__ outd, uint32_t* __restrict__ Z)
{
    constexpr int BM = 128, ST = 36;       // row stride words (conflict-free ldsm phases)
    constexpr int SA = BM * ST;            // one A plane (words)
    constexpr int SB = BN * ST;
    constexpr int WN = BN / 2;
    constexpr int NFR = WN / 8;
    constexpr int NJJ = NFR / 2;

    extern __shared__ uint32_t smw[];
    uint32_t* ah_s = smw;
    uint32_t* al_s = smw + SA;
    uint32_t* bh_s = smw + 2 * SA;
    uint32_t* bl_s = smw + 2 * SA + SB;

    int rel = blockIdx.y;
    const uint32_t* WHr = WTH + (size_t)rel * BN * 64;
    const uint32_t* WLr = WTL + (size_t)rel * BN * 64;
    const float* rs = outd + (size_t)rel * NN;
    int row0 = blockIdx.x * BM;
    int tid  = threadIdx.x;
    int warp = tid >> 5, lane = tid & 31;
    int wm = warp & 3, wn = warp >> 2;
    int m_w = wm * 32, n_w = wn * WN;

    // ldmatrix lane-address components
    int a_r  = lane & 15;                  // row within 16
    int a_kb = (lane >> 4) * 16;           // byte offset for k-high tiles
    int b_r  = (((lane >> 4) << 3) | (lane & 7));   // n row (pair of 8-tiles)
    int b_kb = ((lane >> 3) & 1) * 16;

    uint32_t sa_h = smem_u32(ah_s), sa_l = smem_u32(al_s);
    uint32_t sb_h = smem_u32(bh_s), sb_l = smem_u32(bl_s);

    float acc[2][NFR][4];
    #pragma unroll
    for (int i = 0; i < 2; i++)
        #pragma unroll
        for (int j = 0; j < NFR; j++)
            #pragma unroll
            for (int q = 0; q < 4; q++) acc[i][j][q] = 0.f;

    for (int c = 0; c < 2; c++) {          // two 64-k chunks
        // ---- copy A tile [BM][32w] hi+lo (uint4 vectors): 1024 uint4/plane ----
        #pragma unroll
        for (int u = 0; u < 4; u++) {
            int lin = tid * 4 + u;
            int row = lin >> 3, seg = lin & 7;
            uint4 vh = make_uint4(0, 0, 0, 0), vl = make_uint4(0, 0, 0, 0);
            if (row0 + row < NN) {
                size_t gi = (size_t)(row0 + row) * 16 + c * 8 + seg;  // uint4 units
                vh = *(const uint4*)&XH[gi * 4];
                vl = *(const uint4*)&XL[gi * 4];
            }
            *(uint4*)&ah_s[row * ST + seg * 4] = vh;
            *(uint4*)&al_s[row * ST + seg * 4] = vl;
        }
        // ---- copy B tile [BN][32w] hi+lo: BN*8 uint4/plane ----
        constexpr int NUB = BN * 8 / 256;   // uint4 per thread per plane (FIXED)
        #pragma unroll
        for (int u = 0; u < NUB; u++) {
            int lin = tid * NUB + u;
            int row = lin >> 3, seg = lin & 7;
            size_t gi = (size_t)row * 16 + c * 8 + seg;
            *(uint4*)&bh_s[row * ST + seg * 4] = *(const uint4*)&WHr[gi * 4];
            *(uint4*)&bl_s[row * ST + seg * 4] = *(const uint4*)&WLr[gi * 4];
        }
        __syncthreads();

        #pragma unroll
        for (int kk = 0; kk < 4; kk++) {   // four k16 steps per chunk
            uint32_t ah[2][4], al[2][4];
            #pragma unroll
            for (int i = 0; i < 2; i++) {
                uint32_t off = (uint32_t)((m_w + i * 16 + a_r) * ST) * 4 + a_kb + kk * 32;
                ldsm_x4(ah[i][0], ah[i][1], ah[i][2], ah[i][3], sa_h + off);
                ldsm_x4(al[i][0], al[i][1], al[i][2], al[i][3], sa_l + off);
            }
            #pragma unroll
            for (int jj = 0; jj < NJJ; jj++) {
                uint32_t off = (uint32_t)((n_w + jj * 16 + b_r) * ST) * 4 + b_kb + kk * 32;
                uint32_t bh[4], bl[4];
                ldsm_x4(bh[0], bh[1], bh[2], bh[3], sb_h + off);
                ldsm_x4(bl[0], bl[1], bl[2], bl[3], sb_l + off);
                #pragma unroll
                for (int i = 0; i < 2; i++) {
                    #pragma unroll
                    for (int jt = 0; jt < 2; jt++) {
                        float* a4 = acc[i][jj * 2 + jt];
                        mma_bf16(a4, ah[i], &bh[2 * jt]);
                        mma_bf16(a4, ah[i], &bl[2 * jt]);
                        mma_bf16(a4, al[i], &bh[2 * jt]);
                    }
                }
            }
        }
        __syncthreads();
    }

    // epilogue: scale by outd, pack to half2
    int cr = lane >> 2;
    int cc = (lane & 3) * 2;
    #pragma unroll
    for (int i = 0; i < 2; i++) {
        int r0g = row0 + m_w + i * 16 + cr;
        int r1g = r0g + 8;
        float s0 = (r0g < NN) ? rs[r0g] : 0.f;
        float s1 = (r1g < NN) ? rs[r1g] : 0.f;
        #pragma unroll
        for (int j = 0; j < NFR; j++) {
            int colw = (rel * BN + n_w + j * 8 + cc) >> 1;
            if (r0g < NN) {
                __half2 p = __floats2half2_rn(acc[i][j][0] * s0, acc[i][j][1] * s0);
                Z[(size_t)r0g * WSTW + colw] = *(uint32_t*)&p;
            }
            if (r1g < NN) {
                __half2 p = __floats2half2_rn(acc[i][j][2] * s1, acc[i][j][3] * s1);
                Z[(size_t)r1g * WSTW + colw] = *(uint32_t*)&p;
            }
        }
    }
}

// ------------------------------------------------------------------
// Gather layer 1: warp per dst; emits relu(h1) as packed split planes.
__global__ __launch_bounds__(256) void k_gather128(
    const uint32_t* __restrict__ Z, const float* __restrict__ b1)
{
    int w = (blockIdx.x * blockDim.x + threadIdx.x) >> 5;
    int lane = threadIdx.x & 31;
    if (w >= NN) return;

    float4 tot = make_float4(0.f, 0.f, 0.f, 0.f);
    #pragma unroll
    for (int r = 0; r < NR; r++) {
        float4 b = *(const float4*)&b1[r * 128 + lane * 4];
        tot.x += b.x; tot.y += b.y; tot.z += b.z; tot.w += b.w;

        int idx = r * NN + w;
        int start = g_off[idx];
        int n = g_cnt_in[idx];
        float4 acc = make_float4(0.f, 0.f, 0.f, 0.f);
        int src = (n > 0) ? g_csr[start] : 0;
        for (int j = 0; j < n; j++) {
            int nsrc = (j + 1 < n) ? g_csr[start + j + 1] : 0;
            uint2 v = *(const uint2*)&Z[(size_t)src * 192 + r * 64 + lane * 2];
            float2 f0 = __half22float2(*(__half2*)&v.x);
            float2 f1 = __half22float2(*(__half2*)&v.y);
            acc.x += f0.x; acc.y += f0.y; acc.z += f1.x; acc.w += f1.y;
            src = nsrc;
        }
        float s = g_ind[idx];
        tot.x += s * acc.x; tot.y += s * acc.y; tot.z += s * acc.z; tot.w += s * acc.w;
    }
    // relu + split + pack [row][k2]
    tot.x = fmaxf(tot.x, 0.f); tot.y = fmaxf(tot.y, 0.f);
    tot.z = fmaxf(tot.z, 0.f); tot.w = fmaxf(tot.w, 0.f);
    float h0, l0, h1, l1, h2, l2, h3, l3;
    bsplit(tot.x, h0, l0); bsplit(tot.y, h1, l1);
    bsplit(tot.z, h2, l2); bsplit(tot.w, h3, l3);
    uint2 ph = make_uint2(pack_bf16x2(h0, h1), pack_bf16x2(h2, h3));
    uint2 pl = make_uint2(pack_bf16x2(l0, l1), pack_bf16x2(l2, l3));
    *(uint2*)&g_hh[(size_t)w * 64 + lane * 2] = ph;
    *(uint2*)&g_hl[(size_t)w * 64 + lane * 2] = pl;
}

__global__ __launch_bounds__(256) void k_gather64(
    const uint32_t* __restrict__ Z, const float* __restrict__ b2,
    float* __restrict__ O)
{
    int w = (blockIdx.x * blockDim.x + threadIdx.x) >> 5;
    int lane = threadIdx.x & 31;
    if (w >= NN) return;

    float2 tot = make_float2(0.f, 0.f);
    #pragma unroll
    for (int r = 0; r < NR; r++) {
        float2 b = *(const float2*)&b2[r * 64 + lane * 2];
        tot.x += b.x; tot.y += b.y;

        int idx = r * NN + w;
        int start = g_off[idx];
        int n = g_cnt_in[idx];
        float2 acc = make_float2(0.f, 0.f);
        int src = (n > 0) ? g_csr[start] : 0;
        for (int j = 0; j < n; j++) {
            int nsrc = (j + 1 < n) ? g_csr[start + j + 1] : 0;
            uint32_t v = Z[(size_t)src * 96 + r * 32 + lane];
            float2 f = __half22float2(*(__half2*)&v);
            acc.x += f.x; acc.y += f.y;
            src = nsrc;
        }
        float s = g_ind[idx];
        tot.x += s * acc.x; tot.y += s * acc.y;
    }
    float2 o = make_float2(fmaxf(tot.x, 0.f), fmaxf(tot.y, 0.f));
    *(float2*)&O[(size_t)w * 64 + lane * 2] = o;
}

// ------------------------------------------------------------------
extern "C" void kernel_launch(void* const* d_in, const int* in_sizes, int n_in,
                              void* d_out, int out_size)
{
    const float* x  = (const float*)d_in[0];
    const float* W1 = (const float*)d_in[1];
    const float* b1 = (const float*)d_in[2];
    const float* W2 = (const float*)d_in[3];
    const float* b2 = (const float*)d_in[4];
    const int*   E  = (const int*)d_in[5];
    float* out = (float*)d_out;

    float *poutd;
    uint32_t *pz, *pxh, *pxl, *phh, *phl, *pwh1, *pwl1, *pwh2, *pwl2;
    int *pcin, *pcout, *pcur_g;
    cudaGetSymbolAddress((void**)&pz,    g_z);
    cudaGetSymbolAddress((void**)&poutd, g_outd);
    cudaGetSymbolAddress((void**)&pxh,   g_xh);
    cudaGetSymbolAddress((void**)&pxl,   g_xl);
    cudaGetSymbolAddress((void**)&phh,   g_hh);
    cudaGetSymbolAddress((void**)&phl,   g_hl);
    cudaGetSymbolAddress((void**)&pwh1,  g_wh1);
    cudaGetSymbolAddress((void**)&pwl1,  g_wl1);
    cudaGetSymbolAddress((void**)&pwh2,  g_wh2);
    cudaGetSymbolAddress((void**)&pwl2,  g_wl2);
    cudaGetSymbolAddress((void**)&pcin,  g_cnt_in);
    cudaGetSymbolAddress((void**)&pcout, g_cnt_out);
    cudaGetSymbolAddress((void**)&pcur_g, g_cursor);

    // dynamic smem: A 2*128*36 + B 2*BN*36 words
    const int smem1 = (2 * 128 * 36 + 2 * 128 * 36) * 4;  // 73728
    const int smem2 = (2 * 128 * 36 + 2 * 64 * 36) * 4;   // 55296
    cudaFuncSetAttribute(k_gemm_lm<128, 192>, cudaFuncAttributeMaxDynamicSharedMemorySize, smem1);
    cudaFuncSetAttribute(k_gemm_lm<64, 96>,   cudaFuncAttributeMaxDynamicSharedMemorySize, smem2);

    const int T = 256;

    // zero counters
    cudaMemsetAsync(pcin,  0, NR * NN * sizeof(int));
    cudaMemsetAsync(pcout, 0, NR * NN * sizeof(int));
    cudaMemsetAsync(pcur_g, 0, sizeof(int));

    // CSR + degree build
    k_hist            <<<(NR * NE + T - 1) / T, T>>>(E);
    k_finalize_reserve<<<(NR * NN + T - 1) / T, T>>>();
    k_fill            <<<(NR * NE + T - 1) / T, T>>>(E);

    // pre-split operands
    k_split_x       <<<(NN * 32 + T - 1) / T, T>>>(x);
    k_split_wT<128> <<<(NR * 128 * 64 + T - 1) / T, T>>>(W1, pwh1, pwl1);
    k_split_wT<64>  <<<(NR * 64 * 64 + T - 1) / T, T>>>(W2, pwh2, pwl2);

    // layer 1
    k_gemm_lm<128, 192><<<dim3((NN + 127) / 128, NR), 256, smem1>>>(pxh, pxl, pwh1, pwl1, poutd, pz);
    k_gather128<<<(NN * 32 + T - 1) / T, T>>>(pz, b1);

    // layer 2
    k_gemm_lm<64, 96><<<dim3((NN + 127) / 128, NR), 256, smem2>>>(phh, phl, pwh2, pwl2, poutd, pz);
    k_gather64<<<(NN * 32 + T - 1) / T, T>>>(pz, b2, out);
}

// round 14
// speedup vs baseline: 1.0117x; 1.0117x over previous
#include <cuda_runtime.h>
#include <cuda_bf16.h>
#include <cuda_fp16.h>
#include <cstdint>

#define NN 100000
#define NR 3
#define NE 300000

// ---- device scratch (no allocs allowed) ----
__device__ uint32_t g_z [(size_t)NN * 192];   // transformed feats, half2-packed
__device__ float    g_h1[(size_t)NN * 128];   // layer-1 output (pre-ReLU, f32)
__device__ float    g_outd[NR * NN];
__device__ float    g_ind [NR * NN];
__device__ int      g_cnt_in [NR * NN];
__device__ int      g_cnt_out[NR * NN];
__device__ int      g_off[NR * NN];
__device__ int      g_cur[NR * NN];
__device__ int      g_csr[NR * NE];
__device__ int      g_cursor;

// ------------------------------------------------------------------
__global__ void k_hist(const int* __restrict__ E) {
    int i = blockIdx.x * blockDim.x + threadIdx.x;
    if (i >= NR * NE) return;
    int r = i / NE, e = i % NE;
    const int* Er = E + (size_t)r * 2 * NE;
    atomicAdd(&g_cnt_out[r * NN + Er[e]],      1);
    atomicAdd(&g_cnt_in [r * NN + Er[NE + e]], 1);
}

__global__ void k_finalize_reserve() {
    int i = blockIdx.x * blockDim.x + threadIdx.x;
    int lane = threadIdx.x & 31;
    int d = 0;
    if (i < NR * NN) {
        int cin = g_cnt_in[i];
        g_outd[i] = rsqrtf(fmaxf((float)g_cnt_out[i], 1.f));
        g_ind [i] = rsqrtf(fmaxf((float)cin, 1.f));
        d = cin;
    }
    int s = d;
    #pragma unroll
    for (int o = 1; o < 32; o <<= 1) {
        int t = __shfl_up_sync(0xffffffffu, s, o);
        if (lane >= o) s += t;
    }
    int total = __shfl_sync(0xffffffffu, s, 31);
    int base = 0;
    if (lane == 31) base = atomicAdd(&g_cursor, total);
    base = __shfl_sync(0xffffffffu, base, 31);
    if (i < NR * NN) {
        int start = base + s - d;
        g_off[i] = start;
        g_cur[i] = start;
    }
}

__global__ void k_fill(const int* __restrict__ E) {
    int i = blockIdx.x * blockDim.x + threadIdx.x;
    if (i >= NR * NE) return;
    int r = i / NE, e = i % NE;
    const int* Er = E + (size_t)r * 2 * NE;
    int src = Er[e];
    int dst = Er[NE + e];
    int slot = atomicAdd(&g_cur[r * NN + dst], 1);
    g_csr[slot] = src;
}

// ------------------------------------------------------------------
__device__ __forceinline__ uint32_t pack_bf16x2(float lo, float hi) {
    uint32_t r;
    asm("cvt.rn.bf16x2.f32 %0, %1, %2;" : "=r"(r) : "f"(hi), "f"(lo));
    return r;
}

__device__ __forceinline__ void bsplit(float f, float& h, float& l) {
    __nv_bfloat16 bh = __float2bfloat16_rn(f);
    h = __bfloat162float(bh);
    l = f - h;
}

__device__ __forceinline__ void mma_bf16(float* c, const uint32_t* a, const uint32_t* b) {
    asm volatile(
        "mma.sync.aligned.m16n8k16.row.col.f32.bf16.bf16.f32 "
        "{%0,%1,%2,%3}, {%4,%5,%6,%7}, {%8,%9}, {%0,%1,%2,%3};"
        : "+f"(c[0]), "+f"(c[1]), "+f"(c[2]), "+f"(c[3])
        : "r"(a[0]), "r"(a[1]), "r"(a[2]), "r"(a[3]),
          "r"(b[0]), "r"(b[1]));
}

// Z[row][rel*BN + c] = outd_rel[row] * sum_k relu?(X[row][k]) * W[rel][k][c]
// bf16 2-way split (3 mma passes), m16n8k16. Block 128 x BN, 8 warps (4M x 2N).
template<int BN, int WSTW>
__global__ __launch_bounds__(256) void k_gemm_tc(
    const float* __restrict__ X, const float* __restrict__ W,
    const float* __restrict__ outd, uint32_t* __restrict__ Z, int relu_in)
{
    constexpr int BM = 128, KC = 64;
    constexpr int K2 = KC / 2;
    constexpr int XST = BM + 8;
    constexpr int WST = BN + 8;
    constexpr int SXP = K2 * XST;
    constexpr int SWP = K2 * WST;
    constexpr int WN = BN / 2;
    constexpr int NFR = WN / 8;

    extern __shared__ uint32_t smw[];
    uint32_t* xh = smw;
    uint32_t* xl = smw + SXP;
    uint32_t* wh = smw + 2 * SXP;
    uint32_t* wl = smw + 2 * SXP + SWP;

    int rel = blockIdx.y;
    const float* Wr = W + (size_t)rel * 128 * BN;
    const float* rs = outd + (size_t)rel * NN;
    int row0 = blockIdx.x * BM;
    int tid  = threadIdx.x;
    int warp = tid >> 5, lane = tid & 31;
    int wm = warp & 3, wn = warp >> 2;
    int m_w = wm * 32, n_w = wn * WN;

    float acc[2][NFR][4];
    #pragma unroll
    for (int i = 0; i < 2; i++)
        #pragma unroll
        for (int j = 0; j < NFR; j++)
            #pragma unroll
            for (int q = 0; q < 4; q++) acc[i][j][q] = 0.f;

    for (int k0 = 0; k0 < 128; k0 += KC) {
        #pragma unroll
        for (int t = tid; t < BM * KC / 4; t += 256) {
            int rr = t / (KC / 4);
            int kq = t % (KC / 4);
            int row = row0 + rr;
            float4 v = make_float4(0.f, 0.f, 0.f, 0.f);
            if (row < NN) {
                v = *(const float4*)&X[(size_t)row * 128 + k0 + kq * 4];
                if (relu_in) {
                    v.x = fmaxf(v.x, 0.f); v.y = fmaxf(v.y, 0.f);
                    v.z = fmaxf(v.z, 0.f); v.w = fmaxf(v.w, 0.f);
                }
            }
            float hx, lx, hy, ly, hz, lz, hw, lw;
            bsplit(v.x, hx, lx); bsplit(v.y, hy, ly);
            bsplit(v.z, hz, lz); bsplit(v.w, hw, lw);
            xh[(kq * 2 + 0) * XST + rr] = pack_bf16x2(hx, hy);
            xl[(kq * 2 + 0) * XST + rr] = pack_bf16x2(lx, ly);
            xh[(kq * 2 + 1) * XST + rr] = pack_bf16x2(hz, hw);
            xl[(kq * 2 + 1) * XST + rr] = pack_bf16x2(lz, lw);
        }
        #pragma unroll
        for (int t = tid; t < K2 * BN / 4; t += 256) {
            int k2 = t / (BN / 4);
            int nq = t % (BN / 4);
            float4 v0 = *(const float4*)&Wr[(size_t)(k0 + 2 * k2)     * BN + nq * 4];
            float4 v1 = *(const float4*)&Wr[(size_t)(k0 + 2 * k2 + 1) * BN + nq * 4];
            const float* p0 = &v0.x;
            const float* p1 = &v1.x;
            #pragma unroll
            for (int u = 0; u < 4; u++) {
                float h0, l0, h1, l1;
                bsplit(p0[u], h0, l0);
                bsplit(p1[u], h1, l1);
                wh[k2 * WST + nq * 4 + u] = pack_bf16x2(h0, h1);
                wl[k2 * WST + nq * 4 + u] = pack_bf16x2(l0, l1);
            }
        }
        __syncthreads();

        #pragma unroll
        for (int ks = 0; ks < K2; ks += 8) {
            uint32_t ah[2][4], al[2][4];
            int ar = lane >> 2;
            int ac = ks + (lane & 3);
            #pragma unroll
            for (int i = 0; i < 2; i++) {
                int rb = m_w + i * 16 + ar;
                ah[i][0] = xh[ac * XST + rb];           al[i][0] = xl[ac * XST + rb];
                ah[i][1] = xh[ac * XST + rb + 8];       al[i][1] = xl[ac * XST + rb + 8];
                ah[i][2] = xh[(ac + 4) * XST + rb];     al[i][2] = xl[(ac + 4) * XST + rb];
                ah[i][3] = xh[(ac + 4) * XST + rb + 8]; al[i][3] = xl[(ac + 4) * XST + rb + 8];
            }
            #pragma unroll
            for (int j = 0; j < NFR; j++) {
                int nb = n_w + j * 8 + (lane >> 2);
                int kb = ks + (lane & 3);
                uint32_t bh[2] = { wh[kb * WST + nb], wh[(kb + 4) * WST + nb] };
                uint32_t bl[2] = { wl[kb * WST + nb], wl[(kb + 4) * WST + nb] };
                #pragma unroll
                for (int i = 0; i < 2; i++) {
                    mma_bf16(acc[i][j], ah[i], bh);
                    mma_bf16(acc[i][j], ah[i], bl);
                    mma_bf16(acc[i][j], al[i], bh);
                }
            }
        }
        __syncthreads();
    }

    int cr = lane >> 2;
    int cc = (lane & 3) * 2;
    #pragma unroll
    for (int i = 0; i < 2; i++) {
        int r0g = row0 + m_w + i * 16 + cr;
        int r1g = r0g + 8;
        float s0 = (r0g < NN) ? rs[r0g] : 0.f;
        float s1 = (r1g < NN) ? rs[r1g] : 0.f;
        #pragma unroll
        for (int j = 0; j < NFR; j++) {
            int colw = (rel * BN + n_w + j * 8 + cc) >> 1;
            if (r0g < NN) {
                __half2 p = __floats2half2_rn(acc[i][j][0] * s0, acc[i][j][1] * s0);
                Z[(size_t)r0g * WSTW + colw] = *(uint32_t*)&p;
            }
            if (r1g < NN) {
                __half2 p = __floats2half2_rn(acc[i][j][2] * s1, acc[i][j][3] * s1);
                Z[(size_t)r1g * WSTW + colw] = *(uint32_t*)&p;
            }
        }
    }
}

// ------------------------------------------------------------------
__global__ __launch_bounds__(256) void k_gather128(
    const uint32_t* __restrict__ Z, const float* __restrict__ b1,
    float* __restrict__ O)
{
    int w = (blockIdx.x * blockDim.x + threadIdx.x) >> 5;
    int lane = threadIdx.x & 31;
    if (w >= NN) return;

    float4 tot = make_float4(0.f, 0.f, 0.f, 0.f);
    #pragma unroll
    for (int r = 0; r < NR; r++) {
        float4 b = *(const float4*)&b1[r * 128 + lane * 4];
        tot.x += b.x; tot.y += b.y; tot.z += b.z; tot.w += b.w;

        int idx = r * NN + w;
        int start = g_off[idx];
        int n = g_cnt_in[idx];
        float4 acc = make_float4(0.f, 0.f, 0.f, 0.f);
        int src = (n > 0) ? g_csr[start] : 0;
        for (int j = 0; j < n; j++) {
            int nsrc = (j + 1 < n) ? g_csr[start + j + 1] : 0;
            uint2 v = *(const uint2*)&Z[(size_t)src * 192 + r * 64 + lane * 2];
            float2 f0 = __half22float2(*(__half2*)&v.x);
            float2 f1 = __half22float2(*(__half2*)&v.y);
            acc.x += f0.x; acc.y += f0.y; acc.z += f1.x; acc.w += f1.y;
            src = nsrc;
        }
        float s = g_ind[idx];
        tot.x += s * acc.x; tot.y += s * acc.y; tot.z += s * acc.z; tot.w += s * acc.w;
    }
    *(float4*)&O[(size_t)w * 128 + lane * 4] = tot;
}

__global__ __launch_bounds__(256) void k_gather64(
    const uint32_t* __restrict__ Z, const float* __restrict__ b2,
    float* __restrict__ O)
{
    int w = (blockIdx.x * blockDim.x + threadIdx.x) >> 5;
    int lane = threadIdx.x & 31;
    if (w >= NN) return;

    float2 tot = make_float2(0.f, 0.f);
    #pragma unroll
    for (int r = 0; r < NR; r++) {
        float2 b = *(const float2*)&b2[r * 64 + lane * 2];
        tot.x += b.x; tot.y += b.y;

        int idx = r * NN + w;
        int start = g_off[idx];
        int n = g_cnt_in[idx];
        float2 acc = make_float2(0.f, 0.f);
        int src = (n > 0) ? g_csr[start] : 0;
        for (int j = 0; j < n; j++) {
            int nsrc = (j + 1 < n) ? g_csr[start + j + 1] : 0;
            uint32_t v = Z[(size_t)src * 96 + r * 32 + lane];
            float2 f = __half22float2(*(__half2*)&v);
            acc.x += f.x; acc.y += f.y;
            src = nsrc;
        }
        float s = g_ind[idx];
        tot.x += s * acc.x; tot.y += s * acc.y;
    }
    float2 o = make_float2(fmaxf(tot.x, 0.f), fmaxf(tot.y, 0.f));
    *(float2*)&O[(size_t)w * 64 + lane * 2] = o;
}

// ------------------------------------------------------------------
extern "C" void kernel_launch(void* const* d_in, const int* in_sizes, int n_in,
                              void* d_out, int out_size)
{
    const float* x  = (const float*)d_in[0];
    const float* W1 = (const float*)d_in[1];
    const float* b1 = (const float*)d_in[2];
    const float* W2 = (const float*)d_in[3];
    const float* b2 = (const float*)d_in[4];
    const int*   E  = (const int*)d_in[5];
    float* out = (float*)d_out;

    float *ph1, *poutd;
    uint32_t* pz;
    int *pcin, *pcout, *pcur_g;
    cudaGetSymbolAddress((void**)&pz,    g_z);
    cudaGetSymbolAddress((void**)&ph1,   g_h1);
    cudaGetSymbolAddress((void**)&poutd, g_outd);
    cudaGetSymbolAddress((void**)&pcin,  g_cnt_in);
    cudaGetSymbolAddress((void**)&pcout, g_cnt_out);
    cudaGetSymbolAddress((void**)&pcur_g, g_cursor);

    const int smem1 = (2 * 32 * 136 + 2 * 32 * (128 + 8)) * 4;
    const int smem2 = (2 * 32 * 136 + 2 * 32 * (64 + 8))  * 4;
    cudaFuncSetAttribute(k_gemm_tc<128, 192>, cudaFuncAttributeMaxDynamicSharedMemorySize, smem1);
    cudaFuncSetAttribute(k_gemm_tc<64, 96>,   cudaFuncAttributeMaxDynamicSharedMemorySize, smem2);

    // side stream + events, created once (first call runs outside capture)
    static cudaStream_t s2 = nullptr;
    static cudaEvent_t ev_fork = nullptr, ev_outd = nullptr, ev_join = nullptr;
    if (!s2) {
        cudaStreamCreateWithFlags(&s2, cudaStreamNonBlocking);
        cudaEventCreateWithFlags(&ev_fork, cudaEventDisableTiming);
        cudaEventCreateWithFlags(&ev_outd, cudaEventDisableTiming);
        cudaEventCreateWithFlags(&ev_join, cudaEventDisableTiming);
    }

    const int T = 256;

    // ---- fork CSR/degree chain onto s2 ----
    cudaEventRecord(ev_fork, 0);
    cudaStreamWaitEvent(s2, ev_fork, 0);

    cudaMemsetAsync(pcin,  0, NR * NN * sizeof(int), s2);
    cudaMemsetAsync(pcout, 0, NR * NN * sizeof(int), s2);
    cudaMemsetAsync(pcur_g, 0, sizeof(int), s2);
    k_hist            <<<(NR * NE + T - 1) / T, T, 0, s2>>>(E);
    k_finalize_reserve<<<(NR * NN + T - 1) / T, T, 0, s2>>>();
    cudaEventRecord(ev_outd, s2);            // outd/ind/off ready
    k_fill            <<<(NR * NE + T - 1) / T, T, 0, s2>>>(E);
    cudaEventRecord(ev_join, s2);            // full CSR ready

    // main stream: GEMM1 needs outd only; k_fill overlaps the GEMM
    cudaStreamWaitEvent(0, ev_outd, 0);
    k_gemm_tc<128, 192><<<dim3((NN + 127) / 128, NR), 256, smem1>>>(x, W1, poutd, pz, 0);

    // gather needs the filled CSR too
    cudaStreamWaitEvent(0, ev_join, 0);
    k_gather128<<<(NN * 32 + T - 1) / T, T>>>(pz, b1, ph1);

    // layer 2
    k_gemm_tc<64, 96><<<dim3((NN + 127) / 128, NR), 256, smem2>>>(ph1, W2, poutd, pz, 1);
    k_gather64<<<(NN * 32 + T - 1) / T, T>>>(pz, b2, out);
}